// round 14
// baseline (speedup 1.0000x reference)
#include <cuda_runtime.h>
#include <cstdint>

#define H      100
#define NBATCH 4096
#define SEQ    512
#define TB     28
#define NBLK   148
#define NTHREADS 224           // 7 warps; active: 50 hp * 4 bg = 200
#define NACT   200

// smem (u64 units):
//   Wp [100][208] u64 : row stride 208 u64 = 1664 B (128B-aligned rows)
//                       Wp[k*208 + hp*4 + ty] = (W[ty*100+2hp][k], W[ty*100+2hp+1][k])
//   Hd 2 x [4][101][8] f32 (bg-major): Hd[buf][bg][k][j] = h of batch bg*7+j (j=0..6)
//       bg stride 808 floats (808 % 32 = 8 -> bank-conflict-free across bg)
#define WP_STRIDE 208
#define WP_U64 (100 * WP_STRIDE)     // 20800 u64 = 166,400 B
#define HD_BG  808                   // floats per bg group
#define HD_F   (4 * HD_BG)           // 3232 floats per buffer
#define SMEM_BYTES (WP_U64 * 8 + 2 * HD_F * 4)  // 192,256 B

typedef unsigned long long u64;

__device__ __forceinline__ void fma2(u64 &d, u64 a, u64 b) {
    asm("fma.rn.f32x2 %0, %1, %2, %0;" : "+l"(d) : "l"(a), "l"(b));
}
__device__ __forceinline__ u64 pk(float x, float y) {
    u64 r; asm("mov.b64 %0, {%1, %2};" : "=l"(r) : "f"(x), "f"(y)); return r;
}
__device__ __forceinline__ float2 upk(u64 v) {
    float2 r; asm("mov.b64 {%0, %1}, %2;" : "=f"(r.x), "=f"(r.y) : "l"(v)); return r;
}
__device__ __forceinline__ float tanh_mufu(float v) {
    float r; asm("tanh.approx.f32 %0, %1;" : "=f"(r) : "f"(v)); return r;
}
__device__ __forceinline__ float sig_mufu(float v) {
    return fmaf(0.5f, tanh_mufu(0.5f * v), 0.5f);
}

__global__ void __launch_bounds__(NTHREADS, 1)
lstm_kernel(const float* __restrict__ x,     // [512][4096]
            const float* __restrict__ Wih,   // [400]
            const float* __restrict__ Whh,   // [400][100]
            const float* __restrict__ bih,   // [400]
            const float* __restrict__ bhh,   // [400]
            const float* __restrict__ Wlin,  // [100]
            const float* __restrict__ blin,  // [1]
            float* __restrict__ out)         // [4096]
{
    extern __shared__ u64 sm[];
    u64*   Wp = sm;                       // [k*208 + hp*4 + ty]
    float* Hd = (float*)(sm + WP_U64);    // [buf*HD_F + bg*808 + k*8 + j]

    const int tid = threadIdx.x;
    const int hp  = tid >> 2;   // 0..55; active if < 50 (hidden pair: hu 2hp, 2hp+1)
    const int bg  = tid & 3;    // 0..3  (batch septet: batches bg*7 .. bg*7+6)
    const bool act = (hp < 50);

    // ---- Stage W_hh: pairs over adjacent hidden units, per gate type ----
    for (int idx = tid; idx < 100 * 200; idx += NTHREADS) {
        int k  = idx / 200;
        int q  = idx % 200;
        int ph = q >> 2;
        int ty = q & 3;
        int row0 = ty * 100 + 2 * ph;
        Wp[k * WP_STRIDE + q] = pk(Whh[row0 * 100 + k], Whh[(row0 + 1) * 100 + k]);
    }
    // zero both h buffers (h0 = 0; padding too)
    for (int idx = tid; idx < 2 * HD_F; idx += NTHREADS)
        Hd[idx] = 0.f;

    // ---- per-thread constants: bias sums + W_ih for my 8 gate rows ----
    float bs[2][4], wi[2][4];  // [u][ty], types: 0=i 1=f 2=g 3=o
    if (act) {
        #pragma unroll
        for (int u = 0; u < 2; u++) {
            int hu = 2 * hp + u;
            #pragma unroll
            for (int ty = 0; ty < 4; ty++) {
                int j = ty * 100 + hu;
                bs[u][ty] = bih[j] + bhh[j];
                wi[u][ty] = Wih[j];
            }
        }
    }
    float c[2][7];  // cell state [u][j]
    #pragma unroll
    for (int u = 0; u < 2; u++)
        #pragma unroll
        for (int j = 0; j < 7; j++) c[u][j] = 0.f;

    const int bbase = blockIdx.x * TB + bg * 7;      // my 7 batches (global)
    const float* hbase = Hd + bg * HD_BG;
    float*       sbase = Hd + bg * HD_BG;
    const u64*   wbase = Wp + hp * 4;
    __syncthreads();

    // ---- recurrence over 512 steps ----
    for (int t = 0; t < SEQ; t++) {
        const int cur = (t & 1) ? HD_F : 0;
        const int nxt = (t & 1) ? 0 : HD_F;

        if (act) {
            // x for my 7 batches: scalar loads (bbase NOT vector-aligned).
            float xv[7];
            #pragma unroll
            for (int j = 0; j < 7; j++)
                xv[j] = (bbase + j < NBATCH) ? x[(size_t)t * NBATCH + bbase + j] : 0.f;

            u64 acc[4][7];  // acc[ty][j] = f32x2 over (hu 2hp, 2hp+1)
            #pragma unroll
            for (int ty = 0; ty < 4; ty++)
                #pragma unroll
                for (int j = 0; j < 7; j++) acc[ty][j] = 0ull;

            // ---- software-pipelined GEMM: prefetch k+1 while computing k ----
            ulonglong2 w01 = *(const ulonglong2*)(wbase);
            ulonglong2 w23 = *(const ulonglong2*)(wbase + 2);
            float4 ha = *(const float4*)(hbase + cur);
            float2 hb = *(const float2*)(hbase + cur + 4);
            float  hc = hbase[cur + 6];

            #pragma unroll 4
            for (int k = 0; k < H - 1; k++) {
                // prefetch next iteration's operands FIRST (slack = this k's FMA block)
                const ulonglong2 nw01 = *(const ulonglong2*)(wbase + (k + 1) * WP_STRIDE);
                const ulonglong2 nw23 = *(const ulonglong2*)(wbase + (k + 1) * WP_STRIDE + 2);
                const float4 nha = *(const float4*)(hbase + cur + (k + 1) * 8);
                const float2 nhb = *(const float2*)(hbase + cur + (k + 1) * 8 + 4);
                const float  nhc = hbase[cur + (k + 1) * 8 + 6];

                u64 hd[7];
                hd[0] = pk(ha.x, ha.x); hd[1] = pk(ha.y, ha.y);
                hd[2] = pk(ha.z, ha.z); hd[3] = pk(ha.w, ha.w);
                hd[4] = pk(hb.x, hb.x); hd[5] = pk(hb.y, hb.y);
                hd[6] = pk(hc, hc);
                #pragma unroll
                for (int j = 0; j < 7; j++) {
                    fma2(acc[0][j], w01.x, hd[j]);
                    fma2(acc[1][j], w01.y, hd[j]);
                    fma2(acc[2][j], w23.x, hd[j]);
                    fma2(acc[3][j], w23.y, hd[j]);
                }
                w01 = nw01; w23 = nw23; ha = nha; hb = nhb; hc = nhc;
            }
            {   // final k = H-1 (no prefetch)
                u64 hd[7];
                hd[0] = pk(ha.x, ha.x); hd[1] = pk(ha.y, ha.y);
                hd[2] = pk(ha.z, ha.z); hd[3] = pk(ha.w, ha.w);
                hd[4] = pk(hb.x, hb.x); hd[5] = pk(hb.y, hb.y);
                hd[6] = pk(hc, hc);
                #pragma unroll
                for (int j = 0; j < 7; j++) {
                    fma2(acc[0][j], w01.x, hd[j]);
                    fma2(acc[1][j], w01.y, hd[j]);
                    fma2(acc[2][j], w23.x, hd[j]);
                    fma2(acc[3][j], w23.y, hd[j]);
                }
            }

            // ---- epilogue: gates -> activations -> c,h update ----
            // precompute per-(u,ty,j) input term first (depends only on xv -> ready early)
            float inj[2][4][7];
            #pragma unroll
            for (int u = 0; u < 2; u++)
                #pragma unroll
                for (int ty = 0; ty < 4; ty++)
                    #pragma unroll
                    for (int j = 0; j < 7; j++)
                        inj[u][ty][j] = fmaf(wi[u][ty], xv[j], bs[u][ty]);

            float hn[2][7];
            #pragma unroll
            for (int j = 0; j < 7; j++) {
                float2 gI = upk(acc[0][j]);
                float2 gF = upk(acc[1][j]);
                float2 gG = upk(acc[2][j]);
                float2 gO = upk(acc[3][j]);
                #pragma unroll
                for (int u = 0; u < 2; u++) {
                    float vi = (u ? gI.y : gI.x) + inj[u][0][j];
                    float vf = (u ? gF.y : gF.x) + inj[u][1][j];
                    float vg = (u ? gG.y : gG.x) + inj[u][2][j];
                    float vo = (u ? gO.y : gO.x) + inj[u][3][j];
                    float si = sig_mufu(vi);
                    float sf = sig_mufu(vf);
                    float so = sig_mufu(vo);
                    float tg = tanh_mufu(vg);
                    float cn = fmaf(sf, c[u][j], si * tg);
                    c[u][j] = cn;
                    hn[u][j] = so * tanh_mufu(cn);
                }
            }
            // h store: 2 rows x 7 floats into my bg slab (16B-aligned bases)
            #pragma unroll
            for (int u = 0; u < 2; u++) {
                int hu = 2 * hp + u;
                *(float4*)(sbase + nxt + hu * 8) =
                    make_float4(hn[u][0], hn[u][1], hn[u][2], hn[u][3]);
                *(float2*)(sbase + nxt + hu * 8 + 4) = make_float2(hn[u][4], hn[u][5]);
                sbase[nxt + hu * 8 + 6] = hn[u][6];
            }
        }
        __syncthreads();
    }

    // ---- linear head: out[b] = h_T[b] . W_lin + b_lin ----
    if (tid < TB && blockIdx.x * TB + tid < NBATCH) {
        const int fbg = tid / 7, fj = tid % 7;
        const float* hfin = Hd + fbg * HD_BG;  // SEQ even -> buffer 0
        float acc = blin[0];
        #pragma unroll 4
        for (int k = 0; k < H; k++)
            acc = fmaf(hfin[k * 8 + fj], __ldg(Wlin + k), acc);
        out[blockIdx.x * TB + tid] = acc;
    }
}

extern "C" void kernel_launch(void* const* d_in, const int* in_sizes, int n_in,
                              void* d_out, int out_size) {
    const float* x    = (const float*)d_in[0];
    const float* Wih  = (const float*)d_in[1];
    const float* Whh  = (const float*)d_in[2];
    const float* bih  = (const float*)d_in[3];
    const float* bhh  = (const float*)d_in[4];
    const float* Wlin = (const float*)d_in[5];
    const float* blin = (const float*)d_in[6];

    cudaFuncSetAttribute(lstm_kernel, cudaFuncAttributeMaxDynamicSharedMemorySize, SMEM_BYTES);
    lstm_kernel<<<NBLK, NTHREADS, SMEM_BYTES>>>(x, Wih, Whh, bih, bhh, Wlin, blin,
                                                (float*)d_out);
}

// round 15
// speedup vs baseline: 1.0167x; 1.0167x over previous
#include <cuda_runtime.h>
#include <cstdint>

#define H      100
#define NBATCH 4096
#define SEQ    512
#define TB     28
#define NBLK   148
#define NTHREADS 224           // 7 warps; active: 50 hp * 4 bg = 200
#define NACT   200

// smem (u64 units):
//   Wp [100][208] u64 : row stride 208 u64 = 1664 B (128B-aligned rows)
//                       Wp[k*208 + hp*4 + ty] = (W[ty*100+2hp][k], W[ty*100+2hp+1][k])
//   Hd 2 x [4][101][8] f32 (bg-major): Hd[buf][bg][k][j] = h of batch bg*7+j (j=0..6)
//       bg stride 808 floats (808 % 32 = 8 -> bank-conflict-free across bg)
#define WP_STRIDE 208
#define WP_U64 (100 * WP_STRIDE)     // 20800 u64 = 166,400 B
#define HD_BG  808                   // floats per bg group
#define HD_F   (4 * HD_BG)           // 3232 floats per buffer
#define SMEM_BYTES (WP_U64 * 8 + 2 * HD_F * 4)  // 192,256 B

typedef unsigned long long u64;

__device__ __forceinline__ void fma2(u64 &d, u64 a, u64 b) {
    asm("fma.rn.f32x2 %0, %1, %2, %0;" : "+l"(d) : "l"(a), "l"(b));
}
__device__ __forceinline__ u64 pk(float x, float y) {
    u64 r; asm("mov.b64 %0, {%1, %2};" : "=l"(r) : "f"(x), "f"(y)); return r;
}
__device__ __forceinline__ float2 upk(u64 v) {
    float2 r; asm("mov.b64 {%0, %1}, %2;" : "=f"(r.x), "=f"(r.y) : "l"(v)); return r;
}
__device__ __forceinline__ float tanh_mufu(float v) {
    float r; asm("tanh.approx.f32 %0, %1;" : "=f"(r) : "f"(v)); return r;
}
__device__ __forceinline__ float sig_mufu(float v) {
    return fmaf(0.5f, tanh_mufu(0.5f * v), 0.5f);
}

__global__ void __launch_bounds__(NTHREADS, 1)
lstm_kernel(const float* __restrict__ x,     // [512][4096]
            const float* __restrict__ Wih,   // [400]
            const float* __restrict__ Whh,   // [400][100]
            const float* __restrict__ bih,   // [400]
            const float* __restrict__ bhh,   // [400]
            const float* __restrict__ Wlin,  // [100]
            const float* __restrict__ blin,  // [1]
            float* __restrict__ out)         // [4096]
{
    extern __shared__ u64 sm[];
    u64*   Wp = sm;                       // [k*208 + hp*4 + ty]
    float* Hd = (float*)(sm + WP_U64);    // [buf*HD_F + bg*808 + k*8 + j]

    const int tid = threadIdx.x;
    const int hp  = tid >> 2;   // 0..55; active if < 50 (hidden pair: hu 2hp, 2hp+1)
    const int bg  = tid & 3;    // 0..3  (batch septet: batches bg*7 .. bg*7+6)
    const bool act = (hp < 50);

    // ---- Stage W_hh: pairs over adjacent hidden units, per gate type ----
    for (int idx = tid; idx < 100 * 200; idx += NTHREADS) {
        int k  = idx / 200;
        int q  = idx % 200;
        int ph = q >> 2;
        int ty = q & 3;
        int row0 = ty * 100 + 2 * ph;
        Wp[k * WP_STRIDE + q] = pk(Whh[row0 * 100 + k], Whh[(row0 + 1) * 100 + k]);
    }
    // zero both h buffers (h0 = 0; padding too)
    for (int idx = tid; idx < 2 * HD_F; idx += NTHREADS)
        Hd[idx] = 0.f;

    // ---- per-thread constants: bias sums + W_ih for my 8 gate rows ----
    float bs[2][4], wi[2][4];  // [u][ty], types: 0=i 1=f 2=g 3=o
    if (act) {
        #pragma unroll
        for (int u = 0; u < 2; u++) {
            int hu = 2 * hp + u;
            #pragma unroll
            for (int ty = 0; ty < 4; ty++) {
                int j = ty * 100 + hu;
                bs[u][ty] = bih[j] + bhh[j];
                wi[u][ty] = Wih[j];
            }
        }
    }
    float c[2][7];  // cell state [u][j]
    #pragma unroll
    for (int u = 0; u < 2; u++)
        #pragma unroll
        for (int j = 0; j < 7; j++) c[u][j] = 0.f;

    const int bbase = blockIdx.x * TB + bg * 7;      // my 7 batches (global)
    const float* hbase = Hd + bg * HD_BG;
    float*       sbase = Hd + bg * HD_BG;
    __syncthreads();

    // ---- recurrence over 512 steps ----
    for (int t = 0; t < SEQ; t++) {
        const int cur = (t & 1) ? HD_F : 0;
        const int nxt = (t & 1) ? 0 : HD_F;

        if (act) {
            // x for my 7 batches: scalar loads issued first (LDG latency buried
            // under the whole GEMM; consumed only in epilogue).
            float xv[7];
            #pragma unroll
            for (int j = 0; j < 7; j++)
                xv[j] = (bbase + j < NBATCH) ? x[(size_t)t * NBATCH + bbase + j] : 0.f;

            u64 acc[4][7];  // acc[ty][j] = f32x2 over (hu 2hp, 2hp+1)
            #pragma unroll
            for (int ty = 0; ty < 4; ty++)
                #pragma unroll
                for (int j = 0; j < 7; j++) acc[ty][j] = 0ull;

            #pragma unroll 25
            for (int k = 0; k < H; k++) {
                const ulonglong2 w01 = *(const ulonglong2*)(Wp + k * WP_STRIDE + hp * 4);
                const ulonglong2 w23 = *(const ulonglong2*)(Wp + k * WP_STRIDE + hp * 4 + 2);
                const float4 ha = *(const float4*)(hbase + cur + k * 8);      // j 0..3
                const float2 hb = *(const float2*)(hbase + cur + k * 8 + 4);  // j 4,5
                const float  hc = hbase[cur + k * 8 + 6];                     // j 6
                u64 hd[7];
                hd[0] = pk(ha.x, ha.x); hd[1] = pk(ha.y, ha.y);
                hd[2] = pk(ha.z, ha.z); hd[3] = pk(ha.w, ha.w);
                hd[4] = pk(hb.x, hb.x); hd[5] = pk(hb.y, hb.y);
                hd[6] = pk(hc, hc);
                #pragma unroll
                for (int j = 0; j < 7; j++) {
                    fma2(acc[0][j], w01.x, hd[j]);
                    fma2(acc[1][j], w01.y, hd[j]);
                    fma2(acc[2][j], w23.x, hd[j]);
                    fma2(acc[3][j], w23.y, hd[j]);
                }
            }

            // ---- epilogue: gates -> activations -> c,h update ----
            float hn[2][7];
            #pragma unroll
            for (int j = 0; j < 7; j++) {
                float xb = xv[j];
                float2 gI = upk(acc[0][j]);
                float2 gF = upk(acc[1][j]);
                float2 gG = upk(acc[2][j]);
                float2 gO = upk(acc[3][j]);
                #pragma unroll
                for (int u = 0; u < 2; u++) {
                    float vi = (u ? gI.y : gI.x) + fmaf(wi[u][0], xb, bs[u][0]);
                    float vf = (u ? gF.y : gF.x) + fmaf(wi[u][1], xb, bs[u][1]);
                    float vg = (u ? gG.y : gG.x) + fmaf(wi[u][2], xb, bs[u][2]);
                    float vo = (u ? gO.y : gO.x) + fmaf(wi[u][3], xb, bs[u][3]);
                    float si = sig_mufu(vi);
                    float sf = sig_mufu(vf);
                    float so = sig_mufu(vo);
                    float tg = tanh_mufu(vg);
                    float cn = fmaf(sf, c[u][j], si * tg);
                    c[u][j] = cn;
                    hn[u][j] = so * tanh_mufu(cn);
                }
            }
            // h store: 2 rows x 7 floats into my bg slab (16B-aligned bases)
            #pragma unroll
            for (int u = 0; u < 2; u++) {
                int hu = 2 * hp + u;
                *(float4*)(sbase + nxt + hu * 8) =
                    make_float4(hn[u][0], hn[u][1], hn[u][2], hn[u][3]);
                *(float2*)(sbase + nxt + hu * 8 + 4) = make_float2(hn[u][4], hn[u][5]);
                sbase[nxt + hu * 8 + 6] = hn[u][6];
            }
        }
        __syncthreads();
    }

    // ---- linear head: out[b] = h_T[b] . W_lin + b_lin ----
    if (tid < TB && blockIdx.x * TB + tid < NBATCH) {
        const int fbg = tid / 7, fj = tid % 7;
        const float* hfin = Hd + fbg * HD_BG;  // SEQ even -> buffer 0
        float acc = blin[0];
        #pragma unroll 4
        for (int k = 0; k < H; k++)
            acc = fmaf(hfin[k * 8 + fj], __ldg(Wlin + k), acc);
        out[blockIdx.x * TB + tid] = acc;
    }
}

extern "C" void kernel_launch(void* const* d_in, const int* in_sizes, int n_in,
                              void* d_out, int out_size) {
    const float* x    = (const float*)d_in[0];
    const float* Wih  = (const float*)d_in[1];
    const float* Whh  = (const float*)d_in[2];
    const float* bih  = (const float*)d_in[3];
    const float* bhh  = (const float*)d_in[4];
    const float* Wlin = (const float*)d_in[5];
    const float* blin = (const float*)d_in[6];

    cudaFuncSetAttribute(lstm_kernel, cudaFuncAttributeMaxDynamicSharedMemorySize, SMEM_BYTES);
    lstm_kernel<<<NBLK, NTHREADS, SMEM_BYTES>>>(x, Wih, Whh, bih, bhh, Wlin, blin,
                                                (float*)d_out);
}

// round 16
// speedup vs baseline: 2.5836x; 2.5411x over previous
#include <cuda_runtime.h>
#include <cstdint>

#define H      100
#define NBATCH 4096
#define SEQ    512
#define TB     28
#define NBLK   148
#define NWARP  10
#define NTHREADS 320

#define KSN    13    // k-steps of 8 (K padded 100 -> 104; k=100 ones, k=101 x, 102-103 zero)
#define NTW    5     // n-tiles (8 wide) per warp; n = 4*hu + ty

// smem layout (32-bit words):
//   Wfrag : 50 ptile * 13 ks * 32 lane u64 (B-fragment order)   = 41600 words
//   Ha    : 2 buf * [2 mt * 13 ks * 32 lane * 4 comp] u32       = 2*3328 words
//   Hfin  : [100][32] f32 exact final h                          = 3200 words
#define WF_U64   (50 * KSN * 32)          // 20800 u64
#define HA_U     (2 * KSN * 32 * 4)       // 3328 u32 per buffer
#define SMEM_BYTES ((WF_U64 * 2 + 2 * HA_U + 3200) * 4)  // 205,824 B

typedef unsigned long long u64;

// index of value (m,k) inside one Ha buffer (u32 units), matching m16n8k8 A fragments
__device__ __forceinline__ int FID(int m, int k) {
    return (m >> 4) * 1664 + (k >> 3) * 128 + (m & 7) * 16 + (k & 3) * 4
         + ((m >> 3) & 1) + 2 * ((k >> 2) & 1);
}

__device__ __forceinline__ uint32_t tf32r(float f) {
    uint32_t r; asm("cvt.rna.tf32.f32 %0, %1;" : "=r"(r) : "f"(f)); return r;
}
__device__ __forceinline__ float tanh_mufu(float v) {
    float r; asm("tanh.approx.f32 %0, %1;" : "=f"(r) : "f"(v)); return r;
}
__device__ __forceinline__ float sig_mufu(float v) {
    return fmaf(0.5f, tanh_mufu(0.5f * v), 0.5f);
}
__device__ __forceinline__ void mma8(float* d, const uint4& A, const uint2& B) {
    asm volatile(
        "mma.sync.aligned.m16n8k8.row.col.f32.tf32.tf32.f32 "
        "{%0,%1,%2,%3}, {%4,%5,%6,%7}, {%8,%9}, {%0,%1,%2,%3};"
        : "+f"(d[0]), "+f"(d[1]), "+f"(d[2]), "+f"(d[3])
        : "r"(A.x), "r"(A.y), "r"(A.z), "r"(A.w), "r"(B.x), "r"(B.y));
}

__global__ void __launch_bounds__(NTHREADS, 1)
lstm_kernel(const float* __restrict__ x,     // [512][4096]
            const float* __restrict__ Wih,   // [400]
            const float* __restrict__ Whh,   // [400][100]
            const float* __restrict__ bih,   // [400]
            const float* __restrict__ bhh,   // [400]
            const float* __restrict__ Wlin,  // [100]
            const float* __restrict__ blin,  // [1]
            float* __restrict__ out)         // [4096]
{
    extern __shared__ uint32_t smu[];
    u64*      Wfrag = (u64*)smu;                        // [((p*13+ks)*32+lane)]
    uint32_t* Hab   = smu + WF_U64 * 2;                 // two buffers of HA_U
    float*    Hfin  = (float*)(smu + WF_U64 * 2 + 2 * HA_U);  // [hu][32]

    const int tid  = threadIdx.x;
    const int w    = tid >> 5;
    const int lane = tid & 31;
    const int gid  = lane >> 2;
    const int tig  = lane & 3;

    // ---- stage W into B-fragment order, tf32-rounded; bias in k=100, Wih in k=101 ----
    for (int idx = tid; idx < WF_U64; idx += NTHREADS) {
        int l  = idx & 31;
        int ks = (idx >> 5) % KSN;
        int p  = idx / (KSN * 32);
        int g  = l >> 2, tg = l & 3;
        int hu = 2 * p + (g >> 2);
        int ty = g & 3;
        int row = ty * 100 + hu;
        float v[2];
        #pragma unroll
        for (int h2 = 0; h2 < 2; h2++) {
            int k = 8 * ks + tg + 4 * h2;
            float vv = 0.f;
            if (k < 100)       vv = Whh[row * 100 + k];
            else if (k == 100) vv = bih[row] + bhh[row];
            else if (k == 101) vv = Wih[row];
            v[h2] = vv;
        }
        Wfrag[idx] = (u64)tf32r(v[0]) | ((u64)tf32r(v[1]) << 32);
    }
    // zero both h-fragment buffers
    for (int i = tid; i < 2 * HA_U; i += NTHREADS) Hab[i] = 0;
    __syncthreads();
    // ones column (k=100) into both buffers; x[0] (k=101) into buffer 0
    if (tid < 32) {
        int m = tid;
        uint32_t one = tf32r(1.0f);
        int fi = FID(m, 100);
        Hab[fi] = one;
        Hab[HA_U + fi] = one;
        float xv = 0.f;
        int gb = blockIdx.x * TB + m;
        if (m < TB && gb < NBATCH) xv = x[gb];
        Hab[FID(m, 101)] = tf32r(xv);
    }

    // ---- per-thread cell constants ----
    // cell(mt,nt): m = 16*mt + gid + 8*(tig&1); hu = 10*w + 2*nt + (tig>>1)
    const int modd = tig & 1;
    const int mcell0 = gid + 8 * modd;
    int mpart[2], hupart[5], hucell[5];
    #pragma unroll
    for (int mt = 0; mt < 2; mt++) {
        int m = mcell0 + 16 * mt;
        mpart[mt] = (m >> 4) * 1664 + (m & 7) * 16 + ((m >> 3) & 1);
    }
    #pragma unroll
    for (int nt = 0; nt < NTW; nt++) {
        int hu = 10 * w + 2 * nt + (tig >> 1);
        hucell[nt] = hu;
        hupart[nt] = (hu >> 3) * 128 + (hu & 3) * 4 + 2 * ((hu >> 2) & 1);
    }
    float cst[2][NTW];
    #pragma unroll
    for (int mt = 0; mt < 2; mt++)
        #pragma unroll
        for (int nt = 0; nt < NTW; nt++) cst[mt][nt] = 0.f;

    __syncthreads();

    // ---- recurrence ----
    for (int t = 0; t < SEQ; t++) {
        const uint32_t* Hc = Hab + ((t & 1) ? HA_U : 0);
        uint32_t*       Hn = Hab + ((t & 1) ? 0 : HA_U);

        float d[2][NTW][4];
        #pragma unroll
        for (int mt = 0; mt < 2; mt++)
            #pragma unroll
            for (int nt = 0; nt < NTW; nt++)
                #pragma unroll
                for (int q = 0; q < 4; q++) d[mt][nt][q] = 0.f;

        #pragma unroll
        for (int ks = 0; ks < KSN; ks++) {
            const uint4 A0 = *(const uint4*)(Hc + (ks * 32 + lane) * 4);
            const uint4 A1 = *(const uint4*)(Hc + ((KSN + ks) * 32 + lane) * 4);
            #pragma unroll
            for (int nt = 0; nt < NTW; nt++) {
                const uint2 B = *(const uint2*)(Wfrag + ((5 * w + nt) * KSN + ks) * 32 + lane);
                mma8(d[0][nt], A0, B);
                mma8(d[1][nt], A1, B);
            }
        }

        // ---- epilogue: butterfly gate exchange + cell update ----
        const bool last = (t == SEQ - 1);
        #pragma unroll
        for (int mt = 0; mt < 2; mt++) {
            const int m = mcell0 + 16 * mt;
            const bool live = (m < TB);
            #pragma unroll
            for (int nt = 0; nt < NTW; nt++) {
                float r0 = __shfl_xor_sync(0xffffffffu, d[mt][nt][0], 1);
                float r1 = __shfl_xor_sync(0xffffffffu, d[mt][nt][1], 1);
                float r2 = __shfl_xor_sync(0xffffffffu, d[mt][nt][2], 1);
                float r3 = __shfl_xor_sync(0xffffffffu, d[mt][nt][3], 1);
                float vi = modd ? r2 : d[mt][nt][0];
                float vf = modd ? r3 : d[mt][nt][1];
                float vg = modd ? d[mt][nt][2] : r0;
                float vo = modd ? d[mt][nt][3] : r1;
                if (live) {
                    float si = sig_mufu(vi);
                    float sf = sig_mufu(vf);
                    float so = sig_mufu(vo);
                    float tg = tanh_mufu(vg);
                    float cn = fmaf(sf, cst[mt][nt], si * tg);
                    cst[mt][nt] = cn;
                    float hn = so * tanh_mufu(cn);
                    Hn[mpart[mt] + hupart[nt]] = tf32r(hn);
                    if (last) Hfin[hucell[nt] * 32 + m] = hn;
                }
            }
        }
        // stage x[t+1] into next buffer (k=101 column)
        if (w == 0 && t < SEQ - 1) {
            int m = lane;
            float xv = 0.f;
            int gb = blockIdx.x * TB + m;
            if (m < TB && gb < NBATCH) xv = x[(size_t)(t + 1) * NBATCH + gb];
            Hn[FID(m, 101)] = tf32r(xv);
        }
        __syncthreads();
    }

    // ---- linear head ----
    if (tid < TB) {
        int gb = blockIdx.x * TB + tid;
        if (gb < NBATCH) {
            float acc = blin[0];
            #pragma unroll 4
            for (int k = 0; k < H; k++)
                acc = fmaf(Hfin[k * 32 + tid], __ldg(Wlin + k), acc);
            out[gb] = acc;
        }
    }
}

extern "C" void kernel_launch(void* const* d_in, const int* in_sizes, int n_in,
                              void* d_out, int out_size) {
    const float* x    = (const float*)d_in[0];
    const float* Wih  = (const float*)d_in[1];
    const float* Whh  = (const float*)d_in[2];
    const float* bih  = (const float*)d_in[3];
    const float* bhh  = (const float*)d_in[4];
    const float* Wlin = (const float*)d_in[5];
    const float* blin = (const float*)d_in[6];

    cudaFuncSetAttribute(lstm_kernel, cudaFuncAttributeMaxDynamicSharedMemorySize, SMEM_BYTES);
    lstm_kernel<<<NBLK, NTHREADS, SMEM_BYTES>>>(x, Wih, Whh, bih, bhh, Wlin, blin,
                                                (float*)d_out);
}

// round 17
// speedup vs baseline: 3.6882x; 1.4275x over previous
#include <cuda_runtime.h>
#include <cuda_fp16.h>
#include <cstdint>

#define H      100
#define NBATCH 4096
#define SEQ    512
#define TB     28
#define NBLK   148
#define NWARP  10
#define NTHREADS 320

#define KS     7     // k-steps of 16 (K padded 100 -> 112; k=100 ones, k=101 x, rest 0)
#define NTW    5     // n-tiles (8 wide) per warp; n = 4*hu + ty

// smem (u32 words):
//   Wh   [400][112] half  = 22400 words (staging for B-reg load; aliased by Hfin later)
//   Ha   2 buf * [2 mt][7 ks][32 lane][4 u32] = 2*1792 words (fp16 A fragments)
//   Hfin [100][32] f32 = 3200 words, ALIASES Wh (dead after B regs loaded)
#define WH_U32 (400 * 56)          // 22400
#define HA_U   (2 * KS * 32 * 4)   // 1792 per buffer
#define SMEM_BYTES ((WH_U32 + 2 * HA_U) * 4)   // 103,936 B

__device__ __forceinline__ float tanh_mufu(float v) {
    float r; asm("tanh.approx.f32 %0, %1;" : "=f"(r) : "f"(v)); return r;
}
__device__ __forceinline__ float sig_mufu(float v) {
    return fmaf(0.5f, tanh_mufu(0.5f * v), 0.5f);
}
__device__ __forceinline__ void mma16(float* d, const uint4& A, const uint2& B) {
    asm volatile(
        "mma.sync.aligned.m16n8k16.row.col.f32.f16.f16.f32 "
        "{%0,%1,%2,%3}, {%4,%5,%6,%7}, {%8,%9}, {%0,%1,%2,%3};"
        : "+f"(d[0]), "+f"(d[1]), "+f"(d[2]), "+f"(d[3])
        : "r"(A.x), "r"(A.y), "r"(A.z), "r"(A.w), "r"(B.x), "r"(B.y));
}

__global__ void __launch_bounds__(NTHREADS, 1)
lstm_kernel(const float* __restrict__ x,     // [512][4096]
            const float* __restrict__ Wih,   // [400]
            const float* __restrict__ Whh,   // [400][100]
            const float* __restrict__ bih,   // [400]
            const float* __restrict__ bhh,   // [400]
            const float* __restrict__ Wlin,  // [100]
            const float* __restrict__ blin,  // [1]
            float* __restrict__ out)         // [4096]
{
    extern __shared__ uint32_t smu[];
    uint32_t* Wsm  = smu;                    // [n*56 + k/2], half2 per word
    uint32_t* Hab  = smu + WH_U32;           // 2 x HA_U
    float*    Hfin = (float*)smu;            // aliases Wsm (dead after B-reg load)

    const int tid  = threadIdx.x;
    const int w    = tid >> 5;
    const int lane = tid & 31;
    const int gid  = lane >> 2;
    const int tig  = lane & 3;

    // ---- stage W as fp16 [n][112]: k<100 Whh, k=100 bias, k=101 Wih, else 0 ----
    for (int idx = tid; idx < WH_U32; idx += NTHREADS) {
        int n  = idx / 56;
        int kk = (idx % 56) * 2;
        int row = (n & 3) * 100 + (n >> 2);   // n = 4*hu + ty -> W row = ty*100+hu
        float v[2];
        #pragma unroll
        for (int q = 0; q < 2; q++) {
            int k = kk + q;
            float vv = 0.f;
            if (k < 100)       vv = Whh[row * 100 + k];
            else if (k == 100) vv = bih[row] + bhh[row];
            else if (k == 101) vv = Wih[row];
            v[q] = vv;
        }
        __half2 h2 = __floats2half2_rn(v[0], v[1]);
        Wsm[idx] = *(uint32_t*)&h2;
    }
    // zero both A-fragment buffers
    for (int i = tid; i < 2 * HA_U; i += NTHREADS) Hab[i] = 0;
    __syncthreads();

    // ---- load B fragments into registers (persist across all 512 steps) ----
    uint2 Breg[NTW][KS];
    #pragma unroll
    for (int nt = 0; nt < NTW; nt++) {
        int n = 8 * (5 * w + nt) + gid;
        #pragma unroll
        for (int ks = 0; ks < KS; ks++) {
            int base = n * 56 + ks * 8 + tig;   // u32 of half2 (k=16ks+2tig, +1)
            Breg[nt][ks].x = Wsm[base];
            Breg[nt][ks].y = Wsm[base + 4];     // k += 8
        }
    }
    __syncthreads();   // B regs loaded; Wsm region now dead (Hfin aliases it)

    // ones+x0 column: u32 at (mt*7+6)*128 + (m&7)*16 + 8 + ((m>>3)&1) holds half2(1, x)
    if (tid < 32) {
        int m = tid;
        int xw = ((m >> 4) * 7 + 6) * 128 + (m & 7) * 16 + 8 + ((m >> 3) & 1);
        float xv = 0.f;
        int gb = blockIdx.x * TB + m;
        if (m < TB && gb < NBATCH) xv = x[gb];
        __half2 h2 = __floats2half2_rn(1.0f, xv);
        Hab[xw] = *(uint32_t*)&h2;              // buffer 0 only; buf1 filled at t=0
    }

    // ---- per-thread cell constants ----
    const int modd = tig & 1;
    const int mcell0 = gid + 8 * modd;          // m (mt=0); +16 for mt=1
    float cst[2][NTW];
    #pragma unroll
    for (int mt = 0; mt < 2; mt++)
        #pragma unroll
        for (int nt = 0; nt < NTW; nt++) cst[mt][nt] = 0.f;

    __syncthreads();

    // ---- recurrence ----
    for (int t = 0; t < SEQ; t++) {
        const uint32_t* Hc = Hab + ((t & 1) ? HA_U : 0);
        uint32_t*       Hn = Hab + ((t & 1) ? 0 : HA_U);

        float d[2][NTW][4];
        #pragma unroll
        for (int mt = 0; mt < 2; mt++)
            #pragma unroll
            for (int nt = 0; nt < NTW; nt++)
                #pragma unroll
                for (int q = 0; q < 4; q++) d[mt][nt][q] = 0.f;

        #pragma unroll
        for (int ks = 0; ks < KS; ks++) {
            const uint4 A0 = *(const uint4*)(Hc + ks * 128 + lane * 4);
            const uint4 A1 = *(const uint4*)(Hc + (KS + ks) * 128 + lane * 4);
            #pragma unroll
            for (int nt = 0; nt < NTW; nt++) {
                mma16(d[0][nt], A0, Breg[nt][ks]);
                mma16(d[1][nt], A1, Breg[nt][ks]);
            }
        }

        // ---- epilogue: butterfly gate exchange + cell update ----
        const bool last = (t == SEQ - 1);
        #pragma unroll
        for (int mt = 0; mt < 2; mt++) {
            const int m = mcell0 + 16 * mt;
            const bool live = (m < TB);
            #pragma unroll
            for (int nt = 0; nt < NTW; nt++) {
                float r0 = __shfl_xor_sync(0xffffffffu, d[mt][nt][0], 1);
                float r1 = __shfl_xor_sync(0xffffffffu, d[mt][nt][1], 1);
                float r2 = __shfl_xor_sync(0xffffffffu, d[mt][nt][2], 1);
                float r3 = __shfl_xor_sync(0xffffffffu, d[mt][nt][3], 1);
                float vi = modd ? r2 : d[mt][nt][0];
                float vf = modd ? r3 : d[mt][nt][1];
                float vg = modd ? d[mt][nt][2] : r0;
                float vo = modd ? d[mt][nt][3] : r1;
                if (live) {
                    float si = sig_mufu(vi);
                    float sf = sig_mufu(vf);
                    float so = sig_mufu(vo);
                    float tg = tanh_mufu(vg);
                    float cn = fmaf(sf, cst[mt][nt], si * tg);
                    cst[mt][nt] = cn;
                    float hn = so * tanh_mufu(cn);
                    // store h into A-fragment slot (m, k=hu) as fp16
                    int hu = 10 * w + 2 * nt + (tig >> 1);
                    int kl = hu & 15;
                    int u32i = (mt * KS + (hu >> 4)) * 128 + gid * 16
                             + ((kl & 7) >> 1) * 4 + modd + 2 * ((kl >> 3) & 1);
                    ((__half*)Hn)[u32i * 2 + (hu & 1)] = __float2half(hn);
                    if (last) Hfin[hu * 32 + m] = hn;
                }
            }
        }
        // stage ones + x[t+1] into next buffer
        if (w == 0 && t < SEQ - 1) {
            int m = lane;
            int xw = ((m >> 4) * 7 + 6) * 128 + (m & 7) * 16 + 8 + ((m >> 3) & 1);
            float xv = 0.f;
            int gb = blockIdx.x * TB + m;
            if (m < TB && gb < NBATCH) xv = x[(size_t)(t + 1) * NBATCH + gb];
            __half2 h2 = __floats2half2_rn(1.0f, xv);
            Hn[xw] = *(uint32_t*)&h2;
        }
        __syncthreads();
    }

    // ---- linear head: exact fp32 ----
    if (tid < TB) {
        int gb = blockIdx.x * TB + tid;
        if (gb < NBATCH) {
            float acc = blin[0];
            #pragma unroll 4
            for (int k = 0; k < H; k++)
                acc = fmaf(Hfin[k * 32 + tid], __ldg(Wlin + k), acc);
            out[gb] = acc;
        }
    }
}

extern "C" void kernel_launch(void* const* d_in, const int* in_sizes, int n_in,
                              void* d_out, int out_size) {
    const float* x    = (const float*)d_in[0];
    const float* Wih  = (const float*)d_in[1];
    const float* Whh  = (const float*)d_in[2];
    const float* bih  = (const float*)d_in[3];
    const float* bhh  = (const float*)d_in[4];
    const float* Wlin = (const float*)d_in[5];
    const float* blin = (const float*)d_in[6];

    cudaFuncSetAttribute(lstm_kernel, cudaFuncAttributeMaxDynamicSharedMemorySize, SMEM_BYTES);
    lstm_kernel<<<NBLK, NTHREADS, SMEM_BYTES>>>(x, Wih, Whh, bih, bhh, Wlin, blin,
                                                (float*)d_out);
}